// round 8
// baseline (speedup 1.0000x reference)
#include <cuda_runtime.h>
#include <cstdint>
#include <math_constants.h>

#define TOKENS   32768
#define DIM      2048
#define NE       64
#define TOPK     6

#define BM       128              // tokens per CTA (pass 1)
#define BKT      32               // K per chunk
#define NCHUNK   (DIM / BKT)      // 64
#define THREADS  256              // 8 warps: 4 across M, 2 across N

#define AK       36               // As row stride (floats), conflict-free frag loads
#define WK       36
#define LSTR     66

#define A_STAGE  (BM * AK)
#define W_STAGE  (NE * WK)
#define STAGEF   (A_STAGE + W_STAGE)
#define SMEM_FLOATS (2 * STAGEF + NE)
#define SMEM_BYTES  (SMEM_FLOATS * 4)

#define FLAG_GAP 1e-5f            // ambiguity threshold on biased-score gaps

// ---- flagged-token list (device globals: static allocation, allowed) ----
__device__ int g_flag_count;
__device__ int g_flags[TOKENS];

__global__ void zero_count_kernel() { g_flag_count = 0; }

// round-to-nearest fp32 -> tf32
__device__ __forceinline__ uint32_t rn_tf32(float v) {
    uint32_t r;
    asm("cvt.rna.tf32.f32 %0, %1;" : "=r"(r) : "f"(v));
    return r;
}

__device__ __forceinline__ void mma8(float* c,
                                     uint32_t a0, uint32_t a1, uint32_t a2, uint32_t a3,
                                     uint32_t b0, uint32_t b1) {
    asm volatile(
        "mma.sync.aligned.m16n8k8.row.col.f32.tf32.tf32.f32 "
        "{%0,%1,%2,%3}, {%4,%5,%6,%7}, {%8,%9}, {%0,%1,%2,%3};"
        : "+f"(c[0]), "+f"(c[1]), "+f"(c[2]), "+f"(c[3])
        : "r"(a0), "r"(a1), "r"(a2), "r"(a3), "r"(b0), "r"(b1));
}

// ============================ PASS 1: MMA GEMM + gate ============================
__global__ __launch_bounds__(THREADS, 2)
void gate_kernel(const float* __restrict__ x,
                 const float* __restrict__ w,
                 const float* __restrict__ bias,
                 float* __restrict__ out)
{
    extern __shared__ __align__(16) float sm[];
    float* sBias = sm + 2 * STAGEF;
    float* sLog  = sm;               // epilogue overlay

    const int tid  = threadIdx.x;
    const int lane = tid & 31;
    const int wid  = tid >> 5;
    const int gid  = lane >> 2;
    const int tg   = lane & 3;
    const int m0   = (wid & 3) * 32;
    const int n0   = (wid >> 2) * 32;
    const int block_m = blockIdx.x * BM;

    if (tid < NE) sBias[tid] = bias[tid];

    const float* xg = x + (size_t)block_m * DIM;

    float acc[2][4][4];
    #pragma unroll
    for (int mt = 0; mt < 2; mt++)
        #pragma unroll
        for (int nt = 0; nt < 4; nt++)
            #pragma unroll
            for (int r = 0; r < 4; r++) acc[mt][nt][r] = 0.f;

    float4 xr[4], wr[2];
    int xtok[4], xcq[4], wexp[2], wcq[2];
    #pragma unroll
    for (int i = 0; i < 4; i++) {
        int li = i * THREADS + tid; xtok[i] = li >> 3; xcq[i] = li & 7;
    }
    #pragma unroll
    for (int i = 0; i < 2; i++) {
        int li = i * THREADS + tid; wexp[i] = li >> 3; wcq[i] = li & 7;
    }

    auto ldg_chunk = [&](int c) {
        int k0 = c * BKT;
        #pragma unroll
        for (int i = 0; i < 4; i++)
            xr[i] = *reinterpret_cast<const float4*>(xg + (size_t)xtok[i] * DIM + k0 + xcq[i] * 4);
        #pragma unroll
        for (int i = 0; i < 2; i++)
            wr[i] = *reinterpret_cast<const float4*>(w + (size_t)wexp[i] * DIM + k0 + wcq[i] * 4);
    };
    auto sts_chunk = [&](int s) {
        float* As = sm + s * STAGEF;
        float* Ws = As + A_STAGE;
        #pragma unroll
        for (int i = 0; i < 4; i++)
            *reinterpret_cast<float4*>(&As[xtok[i] * AK + xcq[i] * 4]) = xr[i];
        #pragma unroll
        for (int i = 0; i < 2; i++)
            *reinterpret_cast<float4*>(&Ws[wexp[i] * WK + wcq[i] * 4]) = wr[i];
    };

    ldg_chunk(0);
    sts_chunk(0);
    __syncthreads();
    if (NCHUNK > 1) ldg_chunk(1);

    for (int c = 0; c < NCHUNK; c++) {
        const int s = c & 1;
        if (c + 1 < NCHUNK) {
            sts_chunk(s ^ 1);
            if (c + 2 < NCHUNK) ldg_chunk(c + 2);
        }

        const float* As = sm + s * STAGEF;
        const float* Ws = As + A_STAGE;
        #pragma unroll
        for (int q = 0; q < BKT / 8; q++) {
            const int kb = q * 8;

            // B fragments: 3-term-capable 2-way rna split b ~= bh + bm (err ~2^-22)
            uint32_t bh[4][2], bm[4][2];
            #pragma unroll
            for (int nt = 0; nt < 4; nt++) {
                const float* r = &Ws[(n0 + nt * 8 + gid) * WK + kb + tg];
                #pragma unroll
                for (int j = 0; j < 2; j++) {
                    float b = r[j * 4];
                    uint32_t h = rn_tf32(b);
                    bh[nt][j] = h;
                    bm[nt][j] = rn_tf32(b - __uint_as_float(h));
                }
            }

            #pragma unroll
            for (int mt = 0; mt < 2; mt++) {
                const float* r0 = &As[(m0 + mt * 16 + gid) * AK + kb + tg];
                const float* r1 = r0 + 8 * AK;
                float ar[4] = { r0[0], r1[0], r0[4], r1[4] };
                uint32_t ah[4], am[4];
                #pragma unroll
                for (int r = 0; r < 4; r++) {
                    uint32_t h = rn_tf32(ar[r]);
                    ah[r] = h;
                    am[r] = rn_tf32(ar[r] - __uint_as_float(h));
                }

                #pragma unroll
                for (int nt = 0; nt < 4; nt++) {
                    float* cc = acc[mt][nt];
                    mma8(cc, ah[0], ah[1], ah[2], ah[3], bh[nt][0], bh[nt][1]);  // hi*hi
                    mma8(cc, ah[0], ah[1], ah[2], ah[3], bm[nt][0], bm[nt][1]);  // hi*mid
                    mma8(cc, am[0], am[1], am[2], am[3], bh[nt][0], bh[nt][1]);  // mid*hi
                }
            }
        }
        __syncthreads();
    }

    // ---- dump logits ----
    #pragma unroll
    for (int mt = 0; mt < 2; mt++)
        #pragma unroll
        for (int nt = 0; nt < 4; nt++) {
            int row = m0 + mt * 16 + gid;
            int col = n0 + nt * 8 + tg * 2;
            *reinterpret_cast<float2*>(&sLog[row * LSTR + col]) =
                make_float2(acc[mt][nt][0], acc[mt][nt][1]);
            *reinterpret_cast<float2*>(&sLog[(row + 8) * LSTR + col]) =
                make_float2(acc[mt][nt][2], acc[mt][nt][3]);
        }
    __syncthreads();

    // ---- epilogue: softmax, top-6 + ambiguity flag ----
    if (tid < BM) {
        float* row = sLog + tid * LSTR;

        float m = row[0];
        #pragma unroll
        for (int e = 1; e < NE; e++) m = fmaxf(m, row[e]);
        float ssum = 0.f;
        #pragma unroll
        for (int e = 0; e < NE; e++) { float ex = __expf(row[e] - m); row[e] = ex; ssum += ex; }
        float inv = 1.0f / ssum;
        #pragma unroll
        for (int e = 0; e < NE; e++) row[e] *= inv;

        const int t = block_m + tid;
        float* outw = out + (size_t)t * TOPK;
        float* outi = out + (size_t)TOKENS * TOPK + (size_t)t * TOPK;

        float prev = 0.f, minGap = CUDART_INF_F;
        #pragma unroll
        for (int k = 0; k < TOPK + 1; k++) {           // 7 rounds; last only for gap
            float best = -CUDART_INF_F; int bi = 0;
            #pragma unroll
            for (int e = 0; e < NE; e++) {
                float b = row[e] + sBias[e];
                if (b > best) { best = b; bi = e; }
            }
            if (k > 0) minGap = fminf(minGap, prev - best);
            prev = best;
            if (k < TOPK) {
                outw[k] = row[bi];
                outi[k] = (float)bi;
                row[bi] = -CUDART_INF_F;
            }
        }
        if (minGap < FLAG_GAP) {
            int idx = atomicAdd(&g_flag_count, 1);
            g_flags[idx] = t;
        }
    }
}

// ============ PASS 2: exact scalar recompute for flagged tokens ============
// Bitwise-identical per-logit semantics to the proven scalar kernel:
// single fp32 accumulator, strictly k-ascending FMA chain; identical epilogue.
__global__ __launch_bounds__(256)
void fix_kernel(const float* __restrict__ x,
                const float* __restrict__ w,
                const float* __restrict__ bias,
                float* __restrict__ out)
{
    __shared__ float srow[8][NE];
    const int lane = threadIdx.x & 31;
    const int warp = threadIdx.x >> 5;
    const int gw   = blockIdx.x * 8 + warp;
    const int nwarps = gridDim.x * 8;

    const int n = g_flag_count;
    for (int i = gw; i < n; i += nwarps) {
        const int tok = g_flags[i];
        const float* xt = x + (size_t)tok * DIM;
        const float* w0 = w + (size_t)lane * DIM;
        const float* w1 = w + (size_t)(lane + 32) * DIM;

        float a0 = 0.f, a1 = 0.f;
        for (int k = 0; k < DIM; k += 4) {
            float4 xv  = *reinterpret_cast<const float4*>(xt + k);
            float4 wv0 = *reinterpret_cast<const float4*>(w0 + k);
            float4 wv1 = *reinterpret_cast<const float4*>(w1 + k);
            a0 = fmaf(xv.x, wv0.x, a0); a0 = fmaf(xv.y, wv0.y, a0);
            a0 = fmaf(xv.z, wv0.z, a0); a0 = fmaf(xv.w, wv0.w, a0);
            a1 = fmaf(xv.x, wv1.x, a1); a1 = fmaf(xv.y, wv1.y, a1);
            a1 = fmaf(xv.z, wv1.z, a1); a1 = fmaf(xv.w, wv1.w, a1);
        }
        srow[warp][lane] = a0;
        srow[warp][lane + 32] = a1;
        __syncwarp();

        if (lane == 0) {
            float* row = srow[warp];
            float m = row[0];
            #pragma unroll
            for (int e = 1; e < NE; e++) m = fmaxf(m, row[e]);
            float ssum = 0.f;
            #pragma unroll
            for (int e = 0; e < NE; e++) { float ex = __expf(row[e] - m); row[e] = ex; ssum += ex; }
            float inv = 1.0f / ssum;
            #pragma unroll
            for (int e = 0; e < NE; e++) row[e] *= inv;

            float* outw = out + (size_t)tok * TOPK;
            float* outi = out + (size_t)TOKENS * TOPK + (size_t)tok * TOPK;
            #pragma unroll
            for (int k = 0; k < TOPK; k++) {
                float best = -CUDART_INF_F; int bi = 0;
                #pragma unroll
                for (int e = 0; e < NE; e++) {
                    float b = row[e] + __ldg(&bias[e]);
                    if (b > best) { best = b; bi = e; }
                }
                outw[k] = row[bi];
                outi[k] = (float)bi;
                row[bi] = -CUDART_INF_F;
            }
        }
        __syncwarp();
    }
}

extern "C" void kernel_launch(void* const* d_in, const int* in_sizes, int n_in,
                              void* d_out, int out_size)
{
    const float* x    = (const float*)d_in[0];
    const float* w    = (const float*)d_in[1];
    const float* bias = (const float*)d_in[2];
    float* out = (float*)d_out;

    cudaFuncSetAttribute(gate_kernel, cudaFuncAttributeMaxDynamicSharedMemorySize, SMEM_BYTES);
    zero_count_kernel<<<1, 1>>>();
    gate_kernel<<<TOKENS / BM, THREADS, SMEM_BYTES>>>(x, w, bias, out);
    fix_kernel<<<148, 256>>>(x, w, bias, out);
}